// round 1
// baseline (speedup 1.0000x reference)
#include <cuda_runtime.h>

// Problem constants
#define N_NODES   50000
#define N_EDGES_C 1600000
#define TILE_E    128
#define ETHREADS  512
#define PC_TILE   64

// Scratch: per-node precomputed [vfeat@W1_recv | vfeat@W1_send], 50000 x 256 f32 (51.2 MB)
__device__ float g_P[(size_t)N_NODES * 256];
__device__ int   g_idx64;   // 1 if sender/receiver indices are int64, 0 if int32

// ---------------------------------------------------------------------------
// Detect index dtype: if int64 (little-endian), the high 32-bit words of the
// first 128 elements are all zero (values < 50000). If int32, those words are
// random indices in [0, 50000) -> all-zero is ~impossible.
// ---------------------------------------------------------------------------
__global__ void detect_idx_kernel(const unsigned int* __restrict__ s) {
    __shared__ int flag;
    if (threadIdx.x == 0) flag = 1;
    __syncthreads();
    if (s[2 * threadIdx.x + 1] != 0u) flag = 0;   // benign race: all writers write 0
    __syncthreads();
    if (threadIdx.x == 0) g_idx64 = flag;
}

// ---------------------------------------------------------------------------
// Precompute P[n][j]:
//   j <  128 : sum_k vfeat[n][k] * W1[(64+k)*128 + j]        (receiver slice)
//   j >= 128 : sum_k vfeat[n][k] * W1[(128+k)*128 + (j-128)] (sender slice)
// One CTA per 64-node tile. smem: Wn[64][256] (64KB) + V[64][64] (16KB).
// ---------------------------------------------------------------------------
__global__ void __launch_bounds__(256)
precompute_kernel(const float* __restrict__ vfeat, const float* __restrict__ W1) {
    extern __shared__ float sm[];
    float* sW = sm;               // [64][256]
    float* sV = sm + 64 * 256;    // [64][64]
    const int tid = threadIdx.x;
    const int n0  = blockIdx.x * PC_TILE;

    for (int idx = tid; idx < 64 * 256; idx += 256) {
        int k = idx >> 8, j = idx & 255;
        sW[idx] = (j < 128) ? W1[(64 + k) * 128 + j]
                            : W1[(128 + k) * 128 + (j - 128)];
    }
    for (int idx = tid; idx < PC_TILE * 64; idx += 256) {
        int n = idx >> 6;
        sV[idx] = (n0 + n < N_NODES) ? vfeat[(size_t)(n0 + n) * 64 + (idx & 63)] : 0.0f;
    }
    __syncthreads();

    const int tx = tid & 31;   // 32 col groups * 8 = 256 cols
    const int ty = tid >> 5;   // 8 row groups * 8 = 64 nodes
    float acc[8][8];
#pragma unroll
    for (int i = 0; i < 8; i++)
#pragma unroll
        for (int j = 0; j < 8; j++) acc[i][j] = 0.0f;

    const float* vb = sV + ty * 8 * 64;
    const float* wb = sW + tx * 8;
#pragma unroll 4
    for (int k = 0; k < 64; ++k) {
        float4 wa = *(const float4*)(wb + k * 256);
        float4 wc = *(const float4*)(wb + k * 256 + 4);
        float wv[8] = {wa.x, wa.y, wa.z, wa.w, wc.x, wc.y, wc.z, wc.w};
#pragma unroll
        for (int i = 0; i < 8; i++) {
            float v = vb[i * 64 + k];
#pragma unroll
            for (int j = 0; j < 8; j++) acc[i][j] += v * wv[j];
        }
    }
#pragma unroll
    for (int i = 0; i < 8; i++) {
        int node = n0 + ty * 8 + i;
        if (node < N_NODES) {
            float* dst = g_P + (size_t)node * 256 + tx * 8;
            *(float4*)(dst)     = make_float4(acc[i][0], acc[i][1], acc[i][2], acc[i][3]);
            *(float4*)(dst + 4) = make_float4(acc[i][4], acc[i][5], acc[i][6], acc[i][7]);
        }
    }
}

// ---------------------------------------------------------------------------
// Persistent fused edge kernel. Per 128-edge tile:
//   G[e][j] = P[recv[e]][j] + P[send[e]][128+j] + b1[j]      (gather, smem)
//   H       = relu(G + Xe @ W1a)   (GEMM1: 128x128x64, reg-tiled 4x8/thread)
//   O       = H @ W2 + b2          (GEMM2: 128x64x128, reg-tiled 4x4/thread)
// ---------------------------------------------------------------------------
__global__ void __launch_bounds__(ETHREADS, 1)
edge_kernel(const float* __restrict__ edata,
            const float* __restrict__ W1,
            const float* __restrict__ b1,
            const float* __restrict__ W2,
            const float* __restrict__ b2,
            const void*  __restrict__ senders,
            const void*  __restrict__ receivers,
            float* __restrict__ out) {
    extern __shared__ float sm[];
    float* sW1a = sm;             // [64][128]   8192 f
    float* sW2  = sm + 8192;      // [128][64]   8192 f
    float* sX   = sm + 16384;     // [128][64]   8192 f
    float* sH   = sm + 24576;     // [128][128] 16384 f
    float* sb1  = sm + 40960;     // 128 f
    float* sb2  = sm + 41088;     // 64 f
    int*   sRecv = (int*)(sm + 41152);  // 128 i
    int*   sSend = (int*)(sm + 41280);  // 128 i

    const int tid = threadIdx.x;

    // Stage weights once per CTA (W1a = rows 0..63 of W1 = first 8192 floats)
    for (int idx = tid; idx < 8192; idx += ETHREADS) {
        sW1a[idx] = W1[idx];
        sW2[idx]  = W2[idx];
    }
    if (tid < 128) sb1[tid] = b1[tid];
    if (tid < 64)  sb2[tid] = b2[tid];

    const int idx64 = g_idx64;
    const long long* r64 = (const long long*)receivers;
    const int*       r32 = (const int*)receivers;
    const long long* s64 = (const long long*)senders;
    const int*       s32 = (const int*)senders;

    const int cg = tid & 15;   // 16 col groups
    const int rg = tid >> 4;   // 32 row groups

    for (int tile = blockIdx.x; tile < N_EDGES_C / TILE_E; tile += gridDim.x) {
        const int e0 = tile * TILE_E;
        __syncthreads();  // previous tile's GEMM2 done reading sH / first-iter weights ready

        if (tid < TILE_E) {
            int e = e0 + tid;
            sRecv[tid] = idx64 ? (int)r64[e] : r32[e];
            sSend[tid] = idx64 ? (int)s64[e] : s32[e];
        }
        {
            const float* src = edata + (size_t)e0 * 64;
            for (int idx = tid; idx < TILE_E * 64; idx += ETHREADS)
                sX[idx] = src[idx];
        }
        __syncthreads();

        // Gather G = P_recv + P_send + b1 into sH
        for (int idx = tid; idx < TILE_E * 128; idx += ETHREADS) {
            int e = idx >> 7, j = idx & 127;
            sH[idx] = g_P[(size_t)sRecv[e] * 256 + j]
                    + g_P[(size_t)sSend[e] * 256 + 128 + j]
                    + sb1[j];
        }
        __syncthreads();

        // ---- GEMM1: H[128e x 128h] += X[128e x 64k] @ W1a[64k x 128h]
        float acc[4][8];
#pragma unroll
        for (int i = 0; i < 4; i++)
#pragma unroll
            for (int j = 0; j < 8; j++) acc[i][j] = 0.0f;

        const float* xb = sX + rg * 4 * 64;
        const float* wb = sW1a + cg * 8;
#pragma unroll 4
        for (int k = 0; k < 64; ++k) {
            float4 wa = *(const float4*)(wb + k * 128);
            float4 wc = *(const float4*)(wb + k * 128 + 4);
            float wv[8] = {wa.x, wa.y, wa.z, wa.w, wc.x, wc.y, wc.z, wc.w};
            float xv[4] = {xb[k], xb[64 + k], xb[128 + k], xb[192 + k]};
#pragma unroll
            for (int i = 0; i < 4; i++)
#pragma unroll
                for (int j = 0; j < 8; j++) acc[i][j] += xv[i] * wv[j];
        }
        {
            float* hb = sH + rg * 4 * 128 + cg * 8;
#pragma unroll
            for (int i = 0; i < 4; i++)
#pragma unroll
                for (int j = 0; j < 8; j++)
                    hb[i * 128 + j] = fmaxf(acc[i][j] + hb[i * 128 + j], 0.0f);
        }
        __syncthreads();

        // ---- GEMM2: O[128e x 64o] = H[128e x 128k] @ W2[128k x 64o] + b2
        float acc2[4][4];
#pragma unroll
        for (int i = 0; i < 4; i++)
#pragma unroll
            for (int j = 0; j < 4; j++) acc2[i][j] = 0.0f;

        const float* hb2 = sH + rg * 4 * 128;
        const float* w2b = sW2 + cg * 4;
#pragma unroll 4
        for (int k = 0; k < 128; ++k) {
            float4 w = *(const float4*)(w2b + k * 64);
            float wv[4] = {w.x, w.y, w.z, w.w};
            float hv[4] = {hb2[k], hb2[128 + k], hb2[256 + k], hb2[384 + k]};
#pragma unroll
            for (int i = 0; i < 4; i++)
#pragma unroll
                for (int j = 0; j < 4; j++) acc2[i][j] += hv[i] * wv[j];
        }
        float4 bb = *(const float4*)(sb2 + cg * 4);
#pragma unroll
        for (int i = 0; i < 4; i++) {
            float4 o = make_float4(acc2[i][0] + bb.x, acc2[i][1] + bb.y,
                                   acc2[i][2] + bb.z, acc2[i][3] + bb.w);
            *(float4*)(out + (size_t)(e0 + rg * 4 + i) * 64 + cg * 4) = o;
        }
    }
}

// ---------------------------------------------------------------------------
extern "C" void kernel_launch(void* const* d_in, const int* in_sizes, int n_in,
                              void* d_out, int out_size) {
    const float* edata     = (const float*)d_in[0];
    const float* vfeat     = (const float*)d_in[1];
    const float* W1        = (const float*)d_in[2];
    const float* b1        = (const float*)d_in[3];
    const float* W2        = (const float*)d_in[4];
    const float* b2        = (const float*)d_in[5];
    const void*  senders   = d_in[6];
    const void*  receivers = d_in[7];
    float* out = (float*)d_out;
    (void)in_sizes; (void)n_in; (void)out_size;

    const int pc_smem = (64 * 256 + PC_TILE * 64) * 4;      // 81920 B
    const int e_smem  = (41152 + 256) * 4;                  // 165632 B

    cudaFuncSetAttribute(precompute_kernel,
                         cudaFuncAttributeMaxDynamicSharedMemorySize, pc_smem);
    cudaFuncSetAttribute(edge_kernel,
                         cudaFuncAttributeMaxDynamicSharedMemorySize, e_smem);

    detect_idx_kernel<<<1, 128>>>((const unsigned int*)senders);
    precompute_kernel<<<(N_NODES + PC_TILE - 1) / PC_TILE, 256, pc_smem>>>(vfeat, W1);
    edge_kernel<<<152, ETHREADS, e_smem>>>(edata, W1, b1, W2, b2,
                                           senders, receivers, out);
}

// round 4
// speedup vs baseline: 4.3983x; 4.3983x over previous
#include <cuda_runtime.h>
#include <cuda_bf16.h>
#include <cstdint>

#define N_NODES   50000
#define N_EDGES_C 1600000
#define TILE_E    128
#define PC_TILE   64

// Scratch: per-node precomputed [vfeat@W1_recv | vfeat@W1_send], 50000 x 256 f32 (51.2 MB)
__device__ float g_P[(size_t)N_NODES * 256];
__device__ int   g_idx64;

// ============================ helpers ============================
__device__ __forceinline__ void mma_bf16(float* c, const uint32_t* a, uint32_t b0, uint32_t b1) {
    asm volatile("mma.sync.aligned.m16n8k16.row.col.f32.bf16.bf16.f32 "
        "{%0,%1,%2,%3}, {%4,%5,%6,%7}, {%8,%9}, {%0,%1,%2,%3};"
        : "+f"(c[0]), "+f"(c[1]), "+f"(c[2]), "+f"(c[3])
        : "r"(a[0]), "r"(a[1]), "r"(a[2]), "r"(a[3]), "r"(b0), "r"(b1));
}

__device__ __forceinline__ void split2(float x, float y, uint32_t& hi, uint32_t& lo) {
    __nv_bfloat16 xh = __float2bfloat16(x);
    __nv_bfloat16 yh = __float2bfloat16(y);
    __nv_bfloat16 xl = __float2bfloat16(x - __bfloat162float(xh));
    __nv_bfloat16 yl = __float2bfloat16(y - __bfloat162float(yh));
    __nv_bfloat162 h; h.x = xh; h.y = yh;
    __nv_bfloat162 l; l.x = xl; l.y = yl;
    hi = *reinterpret_cast<uint32_t*>(&h);
    lo = *reinterpret_cast<uint32_t*>(&l);
}

// ---------------------------------------------------------------------------
__global__ void detect_idx_kernel(const unsigned int* __restrict__ s) {
    __shared__ int flag;
    if (threadIdx.x == 0) flag = 1;
    __syncthreads();
    if (s[2 * threadIdx.x + 1] != 0u) flag = 0;
    __syncthreads();
    if (threadIdx.x == 0) g_idx64 = flag;
}

// ---------------------------------------------------------------------------
// Precompute P[n] = [vfeat[n]@W1_recv | vfeat[n]@W1_send] (fp32 exact)
// ---------------------------------------------------------------------------
__global__ void __launch_bounds__(256)
precompute_kernel(const float* __restrict__ vfeat, const float* __restrict__ W1) {
    extern __shared__ char smraw[];
    float* sW = (float*)smraw;               // [64][256]
    float* sV = (float*)smraw + 64 * 256;    // [64][64]
    const int tid = threadIdx.x;
    const int n0  = blockIdx.x * PC_TILE;

    for (int idx = tid; idx < 64 * 256; idx += 256) {
        int k = idx >> 8, j = idx & 255;
        sW[idx] = (j < 128) ? W1[(64 + k) * 128 + j]
                            : W1[(128 + k) * 128 + (j - 128)];
    }
    for (int idx = tid; idx < PC_TILE * 64; idx += 256) {
        int n = idx >> 6;
        sV[idx] = (n0 + n < N_NODES) ? vfeat[(size_t)(n0 + n) * 64 + (idx & 63)] : 0.0f;
    }
    __syncthreads();

    const int tx = tid & 31;
    const int ty = tid >> 5;
    float acc[8][8];
#pragma unroll
    for (int i = 0; i < 8; i++)
#pragma unroll
        for (int j = 0; j < 8; j++) acc[i][j] = 0.0f;

    const float* vb = sV + ty * 8 * 64;
    const float* wb = sW + tx * 8;
#pragma unroll 4
    for (int k = 0; k < 64; ++k) {
        float4 wa = *(const float4*)(wb + k * 256);
        float4 wc = *(const float4*)(wb + k * 256 + 4);
        float wv[8] = {wa.x, wa.y, wa.z, wa.w, wc.x, wc.y, wc.z, wc.w};
#pragma unroll
        for (int i = 0; i < 8; i++) {
            float v = vb[i * 64 + k];
#pragma unroll
            for (int j = 0; j < 8; j++) acc[i][j] += v * wv[j];
        }
    }
#pragma unroll
    for (int i = 0; i < 8; i++) {
        int node = n0 + ty * 8 + i;
        if (node < N_NODES) {
            float* dst = g_P + (size_t)node * 256 + tx * 8;
            *(float4*)(dst)     = make_float4(acc[i][0], acc[i][1], acc[i][2], acc[i][3]);
            *(float4*)(dst + 4) = make_float4(acc[i][4], acc[i][5], acc[i][6], acc[i][7]);
        }
    }
}

// ---------------------------------------------------------------------------
// Persistent HMMA edge kernel. 8 warps/CTA, each warp owns 16 rows of a
// 128-edge tile. Fully register-resident pipeline per warp:
//   acc1 <- gather(P) + b1 (C-fragment layout)
//   acc1 += X@W1a  (mma bf16, 3-term hi/lo split)
//   A2   <- relu(acc1) split to bf16 (C-frag == A-frag layout, regs only)
//   acc2 <- b2 ; acc2 += A2@W2 (mma bf16, 3-term)
//   store acc2
// No __syncthreads in the main loop.
// ---------------------------------------------------------------------------
__global__ void __launch_bounds__(256, 1)
edge_kernel(const float* __restrict__ edata,
            const float* __restrict__ W1,
            const float* __restrict__ b1,
            const float* __restrict__ W2,
            const float* __restrict__ b2,
            const void*  __restrict__ senders,
            const void*  __restrict__ receivers,
            float* __restrict__ out) {
    extern __shared__ char smraw[];
    uint32_t* w1h = (uint32_t*)smraw;        // [16 j][4 s][32 lane][2 reg]
    uint32_t* w1l = w1h + 4096;
    uint32_t* w2h = w1l + 4096;              // [8 j][8 t][32 lane][2 reg]
    uint32_t* w2l = w2h + 4096;
    float* b1f = (float*)(w2l + 4096);       // 128
    float* b2f = b1f + 128;                  // 64

    const int tid = threadIdx.x;
    const int wid = tid >> 5, lid = tid & 31;
    const int gq  = lid >> 2;     // groupID (row within fragment)
    const int tg  = lid & 3;      // thread-in-group (col pair)

    // ---- Stage W1a fragments (k=0..63 rows of W1), fragment-ordered, hi/lo split
    for (int idx = tid; idx < 4096; idx += 256) {
        int reg = idx & 1, lane = (idx >> 1) & 31, s = (idx >> 6) & 3, j = idx >> 8;
        int k = 16 * s + reg * 8 + 2 * (lane & 3);
        int n = 8 * j + (lane >> 2);
        uint32_t hi, lo;
        split2(W1[k * 128 + n], W1[(k + 1) * 128 + n], hi, lo);
        w1h[idx] = hi; w1l[idx] = lo;
    }
    // ---- Stage W2 fragments
    for (int idx = tid; idx < 4096; idx += 256) {
        int reg = idx & 1, lane = (idx >> 1) & 31, t = (idx >> 6) & 7, j = idx >> 9;
        int k = 16 * t + reg * 8 + 2 * (lane & 3);
        int n = 8 * j + (lane >> 2);
        uint32_t hi, lo;
        split2(W2[k * 64 + n], W2[(k + 1) * 64 + n], hi, lo);
        w2h[idx] = hi; w2l[idx] = lo;
    }
    if (tid < 128) b1f[tid] = b1[tid];
    if (tid < 64)  b2f[tid] = b2[tid];
    __syncthreads();

    const int idx64 = g_idx64;
    const long long* r64 = (const long long*)receivers;
    const int*       r32 = (const int*)receivers;
    const long long* s64 = (const long long*)senders;
    const int*       s32 = (const int*)senders;

    const int ntiles = N_EDGES_C / TILE_E;

    for (int tile = blockIdx.x; tile < ntiles; tile += gridDim.x) {
        const int e0  = tile * TILE_E;
        const int em0 = e0 + wid * 16 + gq;   // this lane's first edge row
        const int em1 = em0 + 8;              // second edge row

        const int r0 = idx64 ? (int)r64[em0] : r32[em0];
        const int s0 = idx64 ? (int)s64[em0] : s32[em0];
        const int r1 = idx64 ? (int)r64[em1] : r32[em1];
        const int s1 = idx64 ? (int)s64[em1] : s32[em1];

        const float* pr0 = g_P + (size_t)r0 * 256;
        const float* ps0 = g_P + (size_t)s0 * 256 + 128;
        const float* pr1 = g_P + (size_t)r1 * 256;
        const float* ps1 = g_P + (size_t)s1 * 256 + 128;

        // ---- acc1 init: gather P_recv + P_send + b1 in C-fragment layout
        float c1[16][4];
#pragma unroll
        for (int j = 0; j < 16; j++) {
            int col = 8 * j + 2 * tg;
            float2 a = *(const float2*)(pr0 + col);
            float2 b = *(const float2*)(ps0 + col);
            float2 c = *(const float2*)(pr1 + col);
            float2 d = *(const float2*)(ps1 + col);
            float2 bb = *(const float2*)(b1f + col);
            c1[j][0] = a.x + b.x + bb.x;
            c1[j][1] = a.y + b.y + bb.y;
            c1[j][2] = c.x + d.x + bb.x;
            c1[j][3] = c.y + d.y + bb.y;
        }

        // ---- A1 fragments from edata (bf16 hi/lo split)
        uint32_t ah[4][4], al[4][4];
        const float* x0 = edata + (size_t)em0 * 64;
        const float* x1 = edata + (size_t)em1 * 64;
#pragma unroll
        for (int s = 0; s < 4; s++) {
            int k = 16 * s + 2 * tg;
            float2 v0 = *(const float2*)(x0 + k);
            float2 v1 = *(const float2*)(x1 + k);
            float2 v2 = *(const float2*)(x0 + k + 8);
            float2 v3 = *(const float2*)(x1 + k + 8);
            split2(v0.x, v0.y, ah[s][0], al[s][0]);
            split2(v1.x, v1.y, ah[s][1], al[s][1]);
            split2(v2.x, v2.y, ah[s][2], al[s][2]);
            split2(v3.x, v3.y, ah[s][3], al[s][3]);
        }

        // ---- GEMM1: c1 += Xh@W1h + Xl@W1h + Xh@W1l
#pragma unroll
        for (int j = 0; j < 16; j++) {
#pragma unroll
            for (int s = 0; s < 4; s++) {
                uint2 bh = *(const uint2*)(w1h + ((j * 4 + s) * 32 + lid) * 2);
                uint2 bl = *(const uint2*)(w1l + ((j * 4 + s) * 32 + lid) * 2);
                mma_bf16(c1[j], ah[s], bh.x, bh.y);
                mma_bf16(c1[j], al[s], bh.x, bh.y);
                mma_bf16(c1[j], ah[s], bl.x, bl.y);
            }
        }

        // ---- relu + bf16 split: C-fragment -> A-fragment (register-local)
        uint32_t a2h[8][4], a2l[8][4];
#pragma unroll
        for (int t = 0; t < 8; t++) {
            float v00 = fmaxf(c1[2 * t][0], 0.0f),     v01 = fmaxf(c1[2 * t][1], 0.0f);
            float v10 = fmaxf(c1[2 * t][2], 0.0f),     v11 = fmaxf(c1[2 * t][3], 0.0f);
            float v20 = fmaxf(c1[2 * t + 1][0], 0.0f), v21 = fmaxf(c1[2 * t + 1][1], 0.0f);
            float v30 = fmaxf(c1[2 * t + 1][2], 0.0f), v31 = fmaxf(c1[2 * t + 1][3], 0.0f);
            split2(v00, v01, a2h[t][0], a2l[t][0]);
            split2(v10, v11, a2h[t][1], a2l[t][1]);
            split2(v20, v21, a2h[t][2], a2l[t][2]);
            split2(v30, v31, a2h[t][3], a2l[t][3]);
        }

        // ---- acc2 init from b2
        float d2[8][4];
#pragma unroll
        for (int j = 0; j < 8; j++) {
            float2 bb = *(const float2*)(b2f + 8 * j + 2 * tg);
            d2[j][0] = bb.x; d2[j][1] = bb.y; d2[j][2] = bb.x; d2[j][3] = bb.y;
        }

        // ---- GEMM2: d2 += Hh@W2h + Hl@W2h + Hh@W2l
#pragma unroll
        for (int j = 0; j < 8; j++) {
#pragma unroll
            for (int t = 0; t < 8; t++) {
                uint2 bh = *(const uint2*)(w2h + ((j * 8 + t) * 32 + lid) * 2);
                uint2 bl = *(const uint2*)(w2l + ((j * 8 + t) * 32 + lid) * 2);
                mma_bf16(d2[j], a2h[t], bh.x, bh.y);
                mma_bf16(d2[j], a2l[t], bh.x, bh.y);
                mma_bf16(d2[j], a2h[t], bl.x, bl.y);
            }
        }

        // ---- store
        float* o0 = out + (size_t)em0 * 64;
        float* o1 = out + (size_t)em1 * 64;
#pragma unroll
        for (int j = 0; j < 8; j++) {
            int col = 8 * j + 2 * tg;
            *(float2*)(o0 + col) = make_float2(d2[j][0], d2[j][1]);
            *(float2*)(o1 + col) = make_float2(d2[j][2], d2[j][3]);
        }
    }
}

// ---------------------------------------------------------------------------
extern "C" void kernel_launch(void* const* d_in, const int* in_sizes, int n_in,
                              void* d_out, int out_size) {
    const float* edata     = (const float*)d_in[0];
    const float* vfeat     = (const float*)d_in[1];
    const float* W1        = (const float*)d_in[2];
    const float* b1        = (const float*)d_in[3];
    const float* W2        = (const float*)d_in[4];
    const float* b2        = (const float*)d_in[5];
    const void*  senders   = d_in[6];
    const void*  receivers = d_in[7];
    float* out = (float*)d_out;
    (void)in_sizes; (void)n_in; (void)out_size;

    const int pc_smem = (64 * 256 + PC_TILE * 64) * 4;             // 81920 B
    const int e_smem  = 4 * 4096 * 4 + (128 + 64) * 4;             // 66304 B

    cudaFuncSetAttribute(precompute_kernel,
                         cudaFuncAttributeMaxDynamicSharedMemorySize, pc_smem);
    cudaFuncSetAttribute(edge_kernel,
                         cudaFuncAttributeMaxDynamicSharedMemorySize, e_smem);

    int sms = 0;
    cudaDeviceGetAttribute(&sms, cudaDevAttrMultiProcessorCount, 0);
    if (sms <= 0) sms = 148;

    detect_idx_kernel<<<1, 128>>>((const unsigned int*)senders);
    precompute_kernel<<<(N_NODES + PC_TILE - 1) / PC_TILE, 256, pc_smem>>>(vfeat, W1);
    edge_kernel<<<sms, 256, e_smem>>>(edata, W1, b1, W2, b2,
                                      senders, receivers, out);
}